// round 2
// baseline (speedup 1.0000x reference)
#include <cuda_runtime.h>
#include <math.h>

// ---------------------------------------------------------------------------
// RankingCNN: 3 branches of (conv s32k32 -> GAP -> MLP -> softmax[:,1]) + CAM
// Conv with stride==kernel==32 is a pure patch GEMM:
//   C[M=3072, N=1568] = Wb[3072, K=3072] @ P[K=3072, N=1568]
// where P is im2col of x (k = c*1024 + kh*32 + kw, col = b*49 + i*7 + j).
// Wb's natural flattening IS row-major [3072 x 3072] with exactly that k order.
// ---------------------------------------------------------------------------

#define NBR 3
#define CF 1024
#define BATCH 32
#define KDIM 3072
#define MDIM 3072
#define NDIM 1568          // 32 * 49
#define RANK_OFF 0
#define CAM_OFF 96
#define FEAT_OFF 9504      // 96 + 6*1568
#define FEAT_PER_BRANCH 1605632  // 32*1024*49
#define FEAT_PER_IMG 50176       // 1024*49

// im2col scratch (19.27 MB) — static device array (no allocation)
__device__ float g_P[KDIM * NDIM];

// ---------------------------------------------------------------------------
// Kernel 1: im2col. Writes P row-major [K][N] (coalesced writes; reads are
// strided gathers from x — acceptable, total traffic is small).
// ---------------------------------------------------------------------------
__global__ __launch_bounds__(256) void im2col_kernel(const float* __restrict__ x) {
    int idx = blockIdx.x * blockDim.x + threadIdx.x;
    if (idx >= KDIM * NDIM) return;
    int k = idx / NDIM;
    int col = idx - k * NDIM;
    int c = k >> 10;
    int r = k & 1023;
    int kh = r >> 5;
    int kw = r & 31;
    int b = col / 49;
    int t = col - b * 49;
    int i = t / 7;
    int j = t - i * 7;
    // x[b][c][i*32+kh][j*32+kw]
    g_P[idx] = x[((b * 3 + c) * 224 + i * 32 + kh) * 224 + j * 32 + kw];
}

// ---------------------------------------------------------------------------
// Kernel 2: 128x128x8 register-blocked fp32 GEMM with global->reg prefetch.
// Epilogue adds bias and writes features directly in output layout:
//   out[FEAT_OFF + branch*FPB + b*FPI + o*49 + s]
// ---------------------------------------------------------------------------
__global__ __launch_bounds__(256) void gemm_kernel(const float* __restrict__ A,
                                                   const float* __restrict__ bias,
                                                   float* __restrict__ out) {
    __shared__ float As[8][128];   // A tile, transposed (k-major)
    __shared__ float Bs[8][128];

    const int tid = threadIdx.x;
    const int tx = tid & 15;        // 0..15 -> 8 cols each
    const int ty = tid >> 4;        // 0..15 -> 8 rows each
    const int mBase = blockIdx.y * 128;
    const int nBase = blockIdx.x * 128;

    // A tile load mapping: 128 rows x 8 cols, float4 per thread
    const int aRow = tid >> 1;            // 0..127
    const int aCol = (tid & 1) * 4;       // 0 or 4
    // B tile load mapping: 8 rows x 128 cols, float4 per thread
    const int bRow = tid >> 5;            // 0..7
    const int bCol = (tid & 31) * 4;      // 0..124

    const float* Aptr = A + (mBase + aRow) * KDIM + aCol;
    const float* Bptr = g_P + bRow * NDIM + nBase + bCol;
    const bool bValid = (nBase + bCol) < NDIM;   // NDIM % 4 == 0: float4 all-or-nothing

    float4 aReg = *(const float4*)(Aptr);
    float4 bReg = bValid ? *(const float4*)(Bptr) : make_float4(0.f, 0.f, 0.f, 0.f);

    float acc[8][8];
#pragma unroll
    for (int i = 0; i < 8; i++)
#pragma unroll
        for (int j = 0; j < 8; j++) acc[i][j] = 0.f;

    const int NK = KDIM / 8;
    for (int kt = 0; kt < NK; kt++) {
        // stage current tile into smem
        As[aCol + 0][aRow] = aReg.x;
        As[aCol + 1][aRow] = aReg.y;
        As[aCol + 2][aRow] = aReg.z;
        As[aCol + 3][aRow] = aReg.w;
        *(float4*)&Bs[bRow][bCol] = bReg;
        __syncthreads();

        // prefetch next tile into registers (overlaps with compute)
        if (kt + 1 < NK) {
            aReg = *(const float4*)(Aptr + (kt + 1) * 8);
            bReg = bValid ? *(const float4*)(Bptr + (size_t)(kt + 1) * 8 * NDIM)
                          : make_float4(0.f, 0.f, 0.f, 0.f);
        }

#pragma unroll
        for (int k = 0; k < 8; k++) {
            float a[8], bv[8];
            *(float4*)(a)     = *(const float4*)&As[k][ty * 8];
            *(float4*)(a + 4) = *(const float4*)&As[k][ty * 8 + 4];
            *(float4*)(bv)     = *(const float4*)&Bs[k][tx * 8];
            *(float4*)(bv + 4) = *(const float4*)&Bs[k][tx * 8 + 4];
#pragma unroll
            for (int i = 0; i < 8; i++)
#pragma unroll
                for (int j = 0; j < 8; j++) acc[i][j] = fmaf(a[i], bv[j], acc[i][j]);
        }
        __syncthreads();
    }

    // epilogue: bias + scatter to feature-output layout
#pragma unroll
    for (int i = 0; i < 8; i++) {
        int m = mBase + ty * 8 + i;
        int br = m >> 10;
        int o = m & 1023;
        float bv = bias[m];
        int base = FEAT_OFF + br * FEAT_PER_BRANCH + o * 49;
#pragma unroll
        for (int j = 0; j < 8; j++) {
            int nn = nBase + tx * 8 + j;
            if (nn < NDIM) {
                int b = nn / 49;
                int s = nn - b * 49;
                out[base + b * FEAT_PER_IMG + s] = acc[i][j] + bv;
            }
        }
    }
}

// ---------------------------------------------------------------------------
// Kernel 3: per (branch, image): GAP -> Linear(1024,512)+ReLU -> Linear(512,2)
//           -> softmax -> ranking[b*3 + n]
// ---------------------------------------------------------------------------
__global__ __launch_bounds__(256) void mlp_kernel(const float* __restrict__ outr,
                                                  const float* __restrict__ p1w,
                                                  const float* __restrict__ p1b,
                                                  const float* __restrict__ p2w,
                                                  const float* __restrict__ p2b,
                                                  float* __restrict__ outw) {
    __shared__ float sp[1024];
    __shared__ float sh[512];
    const int n = blockIdx.x >> 5;
    const int b = blockIdx.x & 31;
    const int tid = threadIdx.x;
    const float* f = outr + FEAT_OFF + n * FEAT_PER_BRANCH + b * FEAT_PER_IMG;

    // global average pool over 49 positions
    for (int o = tid; o < 1024; o += 256) {
        const float* fo = f + o * 49;
        float s = 0.f;
#pragma unroll
        for (int q = 0; q < 49; q++) s += fo[q];
        sp[o] = s * (1.0f / 49.0f);
    }
    __syncthreads();

    const int lane = tid & 31;
    const int warp = tid >> 5;
    // Linear 1024 -> 512, one output per warp iteration (coalesced weight reads)
    for (int j = warp; j < 512; j += 8) {
        const float* w = p1w + (n * 512 + j) * 1024;
        float s = 0.f;
        for (int c = lane; c < 1024; c += 32) s = fmaf(sp[c], w[c], s);
#pragma unroll
        for (int off = 16; off; off >>= 1) s += __shfl_xor_sync(0xffffffffu, s, off);
        if (lane == 0) sh[j] = fmaxf(s + p1b[n * 512 + j], 0.f);
    }
    __syncthreads();

    if (warp == 0) {
        const float* w0 = p2w + n * 1024;     // [2][512] per branch
        const float* w1 = w0 + 512;
        float s0 = 0.f, s1 = 0.f;
        for (int c = lane; c < 512; c += 32) {
            float hv = sh[c];
            s0 = fmaf(hv, w0[c], s0);
            s1 = fmaf(hv, w1[c], s1);
        }
#pragma unroll
        for (int off = 16; off; off >>= 1) {
            s0 += __shfl_xor_sync(0xffffffffu, s0, off);
            s1 += __shfl_xor_sync(0xffffffffu, s1, off);
        }
        if (lane == 0) {
            float l0 = s0 + p2b[n * 2 + 0];
            float l1 = s1 + p2b[n * 2 + 1];
            float mx = fmaxf(l0, l1);
            float e0 = expf(l0 - mx);
            float e1 = expf(l1 - mx);
            outw[RANK_OFF + b * 3 + n] = e1 / (e0 + e1);
        }
    }
}

// ---------------------------------------------------------------------------
// Kernel 4: CAM: cam[n][cls][b][s] = relu( sum_o cls_w[n][cls][o] * feats[o][s] )
// Stage feature chunks in smem (contiguous copy) to avoid strided global reads.
// ---------------------------------------------------------------------------
__global__ __launch_bounds__(256) void cam_kernel(const float* __restrict__ outr,
                                                  const float* __restrict__ clsw,
                                                  float* __restrict__ outw) {
    __shared__ float wts[2048];        // [2][1024]
    __shared__ float tile[128 * 49];   // 128-channel chunk of feats
    const int n = blockIdx.x >> 5;
    const int b = blockIdx.x & 31;
    const int tid = threadIdx.x;
    const float* f = outr + FEAT_OFF + n * FEAT_PER_BRANCH + b * FEAT_PER_IMG;

    for (int i = tid; i < 2048; i += 256) wts[i] = clsw[n * 2048 + i];

    const int cls = tid / 49;
    const int s = tid - cls * 49;
    float acc = 0.f;
    for (int ch = 0; ch < 8; ch++) {
        __syncthreads();
        for (int i = tid; i < 128 * 49; i += 256) tile[i] = f[ch * (128 * 49) + i];
        __syncthreads();
        if (tid < 98) {
            const float* w = &wts[cls * 1024 + ch * 128];
#pragma unroll 8
            for (int ol = 0; ol < 128; ol++) acc = fmaf(w[ol], tile[ol * 49 + s], acc);
        }
    }
    if (tid < 98)
        outw[CAM_OFF + (n * 2 + cls) * 1568 + b * 49 + s] = fmaxf(acc, 0.f);
}

// ---------------------------------------------------------------------------
// Launch
// ---------------------------------------------------------------------------
extern "C" void kernel_launch(void* const* d_in, const int* in_sizes, int n_in,
                              void* d_out, int out_size) {
    const float* x    = (const float*)d_in[0];
    const float* Wb   = (const float*)d_in[1];
    const float* bb   = (const float*)d_in[2];
    const float* p1w  = (const float*)d_in[3];
    const float* p1b  = (const float*)d_in[4];
    const float* p2w  = (const float*)d_in[5];
    const float* p2b  = (const float*)d_in[6];
    const float* clsw = (const float*)d_in[7];
    float* out = (float*)d_out;

    const int total = KDIM * NDIM;
    im2col_kernel<<<(total + 255) / 256, 256>>>(x);

    dim3 ggrid((NDIM + 127) / 128, MDIM / 128);   // (13, 24)
    gemm_kernel<<<ggrid, 256>>>(Wb, bb, out);

    mlp_kernel<<<NBR * BATCH, 256>>>(out, p1w, p1b, p2w, p2b, out);
    cam_kernel<<<NBR * BATCH, 256>>>(out, clsw, out);
}

// round 5
// speedup vs baseline: 3.0326x; 3.0326x over previous
#include <cuda_runtime.h>
#include <cuda_fp16.h>
#include <math.h>
#include <stdint.h>

// ---------------------------------------------------------------------------
// RankingCNN: conv(s32,k32) == GEMM C[3072,1568] = Wb[3072,3072] @ P[3072,1568]
// fp32 emulated via fp16 split on legacy tensor cores (mma.sync.m16n8k16):
//   C = Ah*Bh + Ah*Bl + Al*Bh      (fp32 accumulate, residual ~2^-22)
// (tcgen05 is unavailable: harness ptxas target is sm_100, not sm_100a)
// ---------------------------------------------------------------------------

#define NBR 3
#define BATCH 32
#define KDIM 3072
#define MDIM 3072
#define NDIM 1568
#define NPAD 1664            // 13 * 128; pad rows stay zero (static init)
#define RANK_OFF 0
#define CAM_OFF 96
#define FEAT_OFF 9504
#define FPB 1605632          // feats per branch  32*1024*49
#define FPI 50176            // feats per image   1024*49

#define BM 128
#define BN 128
#define BK 32
#define NC (KDIM / BK)       // 96 k-chunks

// smem: row stride 80B (40 fp16) -> conflict-free ldmatrix; tile = 128*80 = 10240B
#define LDS_STRIDE 80
#define TILE_B 10240
#define STAGE_B (4 * TILE_B) // Ah, Al, Bh, Bl
#define SMEM_DYN (2 * STAGE_B)

// ---- static scratch (no allocations allowed) ------------------------------
__device__ __align__(256) __half g_Ah[MDIM * KDIM];
__device__ __align__(256) __half g_Al[MDIM * KDIM];
__device__ __align__(256) __half g_Bh[NPAD * KDIM];   // pad rows never written -> 0
__device__ __align__(256) __half g_Bl[NPAD * KDIM];
__device__ float g_pooled[NBR * BATCH * 1024];
__device__ float g_h[NBR * BATCH * 512];

// ---- PTX helpers ----------------------------------------------------------
__device__ __forceinline__ uint32_t smem_u32(const void* p) {
    uint32_t a;
    asm("{ .reg .u64 t; cvta.to.shared.u64 t, %1; cvt.u32.u64 %0, t; }" : "=r"(a) : "l"(p));
    return a;
}
__device__ __forceinline__ void cp16(uint32_t dst, const void* src) {
    asm volatile("cp.async.cg.shared.global [%0], [%1], 16;" :: "r"(dst), "l"(src));
}
__device__ __forceinline__ void ldmx4(uint32_t* r, uint32_t a) {
    asm volatile("ldmatrix.sync.aligned.m8n8.x4.shared.b16 {%0,%1,%2,%3}, [%4];"
        : "=r"(r[0]), "=r"(r[1]), "=r"(r[2]), "=r"(r[3]) : "r"(a));
}
__device__ __forceinline__ void ldmx2(uint32_t* r, uint32_t a) {
    asm volatile("ldmatrix.sync.aligned.m8n8.x2.shared.b16 {%0,%1}, [%2];"
        : "=r"(r[0]), "=r"(r[1]) : "r"(a));
}
__device__ __forceinline__ void mma16816(float* c, const uint32_t* a, const uint32_t* b) {
    asm volatile("mma.sync.aligned.m16n8k16.row.col.f32.f16.f16.f32 "
        "{%0,%1,%2,%3}, {%4,%5,%6,%7}, {%8,%9}, {%0,%1,%2,%3};"
        : "+f"(c[0]), "+f"(c[1]), "+f"(c[2]), "+f"(c[3])
        : "r"(a[0]), "r"(a[1]), "r"(a[2]), "r"(a[3]), "r"(b[0]), "r"(b[1]));
}

// ---------------------------------------------------------------------------
// Kernel 1: Wb fp32 -> fp16 (hi, lo)
// ---------------------------------------------------------------------------
__global__ __launch_bounds__(256) void conv_a_kernel(const float* __restrict__ Wb) {
    int i2 = (blockIdx.x * 256 + threadIdx.x) * 2;
    if (i2 >= MDIM * KDIM) return;
    float2 v = *(const float2*)(Wb + i2);
    __half h0 = __float2half(v.x), h1 = __float2half(v.y);
    __half l0 = __float2half(v.x - __half2float(h0));
    __half l1 = __float2half(v.y - __half2float(h1));
    *(__half2*)(g_Ah + i2) = __half2(h0, h1);
    *(__half2*)(g_Al + i2) = __half2(l0, l1);
}

// ---------------------------------------------------------------------------
// Kernel 2: fused im2col + fp16 split: Bt[n][k], k = c*1024 + kh*32 + kw
// ---------------------------------------------------------------------------
__global__ __launch_bounds__(256) void im2col_kernel(const float* __restrict__ x) {
    int i2 = (blockIdx.x * 256 + threadIdx.x) * 2;
    if (i2 >= NDIM * KDIM) return;
    int n = i2 / KDIM;
    int k = i2 - n * KDIM;          // even
    int c = k >> 10, r = k & 1023, kh = r >> 5, kw = r & 31;
    int b = n / 49, t = n - b * 49, ii = t / 7, jj = t - ii * 7;
    const float* src = x + ((size_t)(b * 3 + c) * 224 + ii * 32 + kh) * 224 + jj * 32 + kw;
    float2 v = *(const float2*)src;
    __half h0 = __float2half(v.x), h1 = __float2half(v.y);
    __half l0 = __float2half(v.x - __half2float(h0));
    __half l1 = __float2half(v.y - __half2float(h1));
    *(__half2*)(g_Bh + i2) = __half2(h0, h1);
    *(__half2*)(g_Bl + i2) = __half2(l0, l1);
}

// ---------------------------------------------------------------------------
// Kernel 3: mma.sync GEMM, tile 128x128x32, 8 warps (2m x 4n), warp 64x32,
// cp.async double-buffered. 3 fp16 terms into fp32 accumulators.
// ---------------------------------------------------------------------------
__global__ __launch_bounds__(256, 1) void gemm_mma_kernel(const float* __restrict__ bias,
                                                          float* __restrict__ out) {
    extern __shared__ char smem[];
    const uint32_t s0 = smem_u32(smem);

    const int tid = threadIdx.x;
    const int wid = tid >> 5;
    const int lane = tid & 31;
    const int mBase = blockIdx.y * BM;
    const int nBase = blockIdx.x * BN;

    // ---- load mapping: 2 uint4 per thread per tile -------------------------
    const int r0 = tid >> 2;            // 0..63
    const int seg = tid & 3;            // 16B segment within 64B row
    const uint32_t sOff0 = (uint32_t)(r0 * LDS_STRIDE + seg * 16);
    const uint32_t sOff1 = sOff0 + 64 * LDS_STRIDE;

    const __half* gAh = g_Ah + (size_t)(mBase + r0) * KDIM + seg * 8;
    const __half* gAl = g_Al + (size_t)(mBase + r0) * KDIM + seg * 8;
    const __half* gBh = g_Bh + (size_t)(nBase + r0) * KDIM + seg * 8;
    const __half* gBl = g_Bl + (size_t)(nBase + r0) * KDIM + seg * 8;
    const size_t rowJump = (size_t)64 * KDIM;

    float acc[4][4][4];
#pragma unroll
    for (int i = 0; i < 4; i++)
#pragma unroll
        for (int j = 0; j < 4; j++)
#pragma unroll
            for (int q = 0; q < 4; q++) acc[i][j][q] = 0.f;

    // ---- ldmatrix base addresses (per warp/lane) ---------------------------
    const int wm = wid & 1;             // 0..1 -> 64-row half
    const int wn = wid >> 1;            // 0..3 -> 32-col quarter
    const uint32_t aBase = (uint32_t)((wm * 64 + (lane & 15)) * LDS_STRIDE + ((lane >> 4) * 8) * 2);
    const uint32_t bBase = (uint32_t)(2 * TILE_B + (wn * 32 + (lane & 7)) * LDS_STRIDE
                                      + (((lane >> 3) & 1) * 8) * 2);

#define ISSUE(kt) do {                                                          \
        const uint32_t d = s0 + (((kt) & 1) ? STAGE_B : 0);                     \
        const int k0 = (kt) * BK;                                               \
        cp16(d + sOff0,              gAh + k0);                                 \
        cp16(d + sOff1,              gAh + rowJump + k0);                       \
        cp16(d + TILE_B + sOff0,     gAl + k0);                                 \
        cp16(d + TILE_B + sOff1,     gAl + rowJump + k0);                       \
        cp16(d + 2*TILE_B + sOff0,   gBh + k0);                                 \
        cp16(d + 2*TILE_B + sOff1,   gBh + rowJump + k0);                       \
        cp16(d + 3*TILE_B + sOff0,   gBl + k0);                                 \
        cp16(d + 3*TILE_B + sOff1,   gBl + rowJump + k0);                       \
    } while (0)

    ISSUE(0);
    asm volatile("cp.async.commit_group;");

    for (int kt = 0; kt < NC; kt++) {
        if (kt + 1 < NC) ISSUE(kt + 1);
        asm volatile("cp.async.commit_group;");
        if (kt + 1 < NC) asm volatile("cp.async.wait_group 1;");
        else             asm volatile("cp.async.wait_group 0;");
        __syncthreads();

        const uint32_t sb = s0 + ((kt & 1) ? STAGE_B : 0);
        const uint32_t aB = sb + aBase;
        const uint32_t bB = sb + bBase;

#pragma unroll
        for (int ks = 0; ks < 2; ks++) {
            const uint32_t kOff = (uint32_t)(ks * 32);   // 16 fp16 = 32B
            uint32_t ah[4][4], al[4][4], bh[4][2], bl[4][2];
#pragma unroll
            for (int mf = 0; mf < 4; mf++) ldmx4(ah[mf], aB + mf * (16 * LDS_STRIDE) + kOff);
#pragma unroll
            for (int nf = 0; nf < 4; nf++) ldmx2(bh[nf], bB + nf * (8 * LDS_STRIDE) + kOff);
#pragma unroll
            for (int nf = 0; nf < 4; nf++) ldmx2(bl[nf], bB + TILE_B + nf * (8 * LDS_STRIDE) + kOff);
#pragma unroll
            for (int mf = 0; mf < 4; mf++) ldmx4(al[mf], aB + TILE_B + mf * (16 * LDS_STRIDE) + kOff);

#pragma unroll
            for (int mf = 0; mf < 4; mf++)
#pragma unroll
                for (int nf = 0; nf < 4; nf++) {
                    mma16816(acc[mf][nf], ah[mf], bh[nf]);
                    mma16816(acc[mf][nf], ah[mf], bl[nf]);
                    mma16816(acc[mf][nf], al[mf], bh[nf]);
                }
        }
        __syncthreads();
    }

    // ---- epilogue: bias + scatter to feature layout ------------------------
#pragma unroll
    for (int mf = 0; mf < 4; mf++) {
        const int m0 = mBase + wm * 64 + mf * 16 + (lane >> 2);
        const int m1 = m0 + 8;
        const float bv0 = bias[m0], bv1 = bias[m1];
        float* ob0 = out + FEAT_OFF + (size_t)(m0 >> 10) * FPB + (size_t)(m0 & 1023) * 49;
        float* ob1 = out + FEAT_OFF + (size_t)(m1 >> 10) * FPB + (size_t)(m1 & 1023) * 49;
#pragma unroll
        for (int nf = 0; nf < 4; nf++) {
            const int n = nBase + wn * 32 + nf * 8 + (lane & 3) * 2;
            if (n < NDIM) {
                int b0 = n / 49,     sA = n - b0 * 49;
                int b1 = (n+1) / 49, sB = (n+1) - b1 * 49;
                ob0[(size_t)b0 * FPI + sA] = acc[mf][nf][0] + bv0;
                ob0[(size_t)b1 * FPI + sB] = acc[mf][nf][1] + bv0;
                ob1[(size_t)b0 * FPI + sA] = acc[mf][nf][2] + bv1;
                ob1[(size_t)b1 * FPI + sB] = acc[mf][nf][3] + bv1;
            }
        }
    }
#undef ISSUE
}

// ---------------------------------------------------------------------------
// Kernel 4: global average pool -> g_pooled[n][b][1024]
// ---------------------------------------------------------------------------
__global__ __launch_bounds__(256) void gap_kernel(const float* __restrict__ out) {
    const int n = blockIdx.x >> 5, b = blockIdx.x & 31;
    const float* f = out + FEAT_OFF + (size_t)n * FPB + (size_t)b * FPI;
    float* dst = g_pooled + (n * 32 + b) * 1024;
    for (int ch = threadIdx.x; ch < 1024; ch += 256) {
        const float* fo = f + ch * 49;
        float s = 0.f;
#pragma unroll
        for (int q = 0; q < 49; q++) s += fo[q];
        dst[ch] = s * (1.0f / 49.0f);
    }
}

// ---------------------------------------------------------------------------
// Kernel 5: Linear(1024,512)+ReLU, weight-streamed
// ---------------------------------------------------------------------------
__global__ __launch_bounds__(256) void mlp1_kernel(const float* __restrict__ p1w,
                                                   const float* __restrict__ p1b) {
    const int branch = blockIdx.y;
    const int wid = threadIdx.x >> 5, lane = threadIdx.x & 31;
    const int j = blockIdx.x * 8 + wid;
    const float* w = p1w + (size_t)(branch * 512 + j) * 1024;
    float wr[32];
#pragma unroll
    for (int t = 0; t < 32; t++) wr[t] = w[t * 32 + lane];
    const float bj = p1b[branch * 512 + j];
    for (int b = 0; b < 32; b++) {
        const float* pp = g_pooled + (branch * 32 + b) * 1024;
        float s = 0.f;
#pragma unroll
        for (int t = 0; t < 32; t++) s = fmaf(wr[t], pp[t * 32 + lane], s);
#pragma unroll
        for (int off = 16; off; off >>= 1) s += __shfl_xor_sync(0xffffffffu, s, off);
        if (lane == 0) g_h[(branch * 32 + b) * 512 + j] = fmaxf(s + bj, 0.f);
    }
}

// ---------------------------------------------------------------------------
// Kernel 6: Linear(512,2) + softmax[:,1] -> ranking
// ---------------------------------------------------------------------------
__global__ __launch_bounds__(256) void mlp2_kernel(const float* __restrict__ p2w,
                                                   const float* __restrict__ p2b,
                                                   float* __restrict__ out) {
    const int branch = blockIdx.x;
    const int wid = threadIdx.x >> 5, lane = threadIdx.x & 31;
    const float* w0 = p2w + branch * 1024;
    const float* w1 = w0 + 512;
    for (int b = wid; b < 32; b += 8) {
        const float* h = g_h + (branch * 32 + b) * 512;
        float s0 = 0.f, s1 = 0.f;
        for (int t = lane; t < 512; t += 32) {
            float hv = h[t];
            s0 = fmaf(hv, w0[t], s0);
            s1 = fmaf(hv, w1[t], s1);
        }
#pragma unroll
        for (int off = 16; off; off >>= 1) {
            s0 += __shfl_xor_sync(0xffffffffu, s0, off);
            s1 += __shfl_xor_sync(0xffffffffu, s1, off);
        }
        if (lane == 0) {
            float l0 = s0 + p2b[branch * 2 + 0];
            float l1 = s1 + p2b[branch * 2 + 1];
            float mx = fmaxf(l0, l1);
            float e0 = expf(l0 - mx), e1 = expf(l1 - mx);
            out[RANK_OFF + b * 3 + branch] = e1 / (e0 + e1);
        }
    }
}

// ---------------------------------------------------------------------------
// Kernel 7: CAM — 98 dot-products of length 1024 per (branch,image)
// ---------------------------------------------------------------------------
__global__ __launch_bounds__(256) void cam_kernel(const float* __restrict__ out_r,
                                                  const float* __restrict__ clsw,
                                                  float* __restrict__ out_w) {
    __shared__ float wts[2048];
    __shared__ float tile[128 * 49];
    const int n = blockIdx.x >> 5, b = blockIdx.x & 31;
    const int tid = threadIdx.x, w = tid >> 5, lane = tid & 31;
    const float* f = out_r + FEAT_OFF + (size_t)n * FPB + (size_t)b * FPI;

    for (int i = tid; i < 2048; i += 256) wts[i] = clsw[n * 2048 + i];

    const int nd = (w < 2) ? 13 : 12;
    float acc[13];
#pragma unroll
    for (int i = 0; i < 13; i++) acc[i] = 0.f;

    for (int ch = 0; ch < 8; ch++) {
        __syncthreads();
        for (int i = tid; i < 128 * 49; i += 256) tile[i] = f[ch * (128 * 49) + i];
        __syncthreads();
#pragma unroll
        for (int di = 0; di < 13; di++) {
            if (di >= nd) break;
            int d = w + di * 8;
            int cls = d / 49, s = d - cls * 49;
            const float* wp = wts + cls * 1024 + ch * 128;
            float a = acc[di];
#pragma unroll
            for (int o4 = 0; o4 < 4; o4++)
                a = fmaf(wp[o4 * 32 + lane], tile[(o4 * 32 + lane) * 49 + s], a);
            acc[di] = a;
        }
    }
#pragma unroll
    for (int di = 0; di < 13; di++) {
        if (di >= nd) break;
        float a = acc[di];
#pragma unroll
        for (int off = 16; off; off >>= 1) a += __shfl_xor_sync(0xffffffffu, a, off);
        if (lane == 0) {
            int d = w + di * 8;
            int cls = d / 49, s = d - cls * 49;
            out_w[CAM_OFF + (n * 2 + cls) * 1568 + b * 49 + s] = fmaxf(a, 0.f);
        }
    }
}

// ---------------------------------------------------------------------------
// Launch
// ---------------------------------------------------------------------------
extern "C" void kernel_launch(void* const* d_in, const int* in_sizes, int n_in,
                              void* d_out, int out_size) {
    const float* x    = (const float*)d_in[0];
    const float* Wb   = (const float*)d_in[1];
    const float* bb   = (const float*)d_in[2];
    const float* p1w  = (const float*)d_in[3];
    const float* p1b  = (const float*)d_in[4];
    const float* p2w  = (const float*)d_in[5];
    const float* p2b  = (const float*)d_in[6];
    const float* clsw = (const float*)d_in[7];
    float* out = (float*)d_out;

    conv_a_kernel<<<(MDIM * KDIM / 2 + 255) / 256, 256>>>(Wb);
    im2col_kernel<<<(NDIM * KDIM / 2 + 255) / 256, 256>>>(x);

    cudaFuncSetAttribute(gemm_mma_kernel, cudaFuncAttributeMaxDynamicSharedMemorySize, SMEM_DYN);
    dim3 ggrid(NPAD / BN, MDIM / BM);   // (13, 24)
    gemm_mma_kernel<<<ggrid, 256, SMEM_DYN>>>(bb, out);

    gap_kernel<<<NBR * BATCH, 256>>>(out);
    mlp1_kernel<<<dim3(64, NBR), 256>>>(p1w, p1b);
    mlp2_kernel<<<NBR, 256>>>(p2w, p2b, out);
    cam_kernel<<<NBR * BATCH, 256>>>(out, clsw, out);
}

// round 6
// speedup vs baseline: 3.4896x; 1.1507x over previous
#include <cuda_runtime.h>
#include <cuda_fp16.h>
#include <math.h>
#include <stdint.h>

// ---------------------------------------------------------------------------
// RankingCNN: conv(s32,k32) == GEMM C[3072,1568] = Wb[3072,3072] @ P[3072,1568]
// fp32 via fp16 split on legacy tensor cores (mma.sync.m16n8k16):
//   C = Ah*Bh (fp32 acc) + [Ah*Bl + Al*Bh] (fp16 acc, merged at end)
// BK=64, 3-stage cp.async pipeline, SW128-swizzled smem, 1 barrier/chunk.
// ---------------------------------------------------------------------------

#define NBR 3
#define BATCH 32
#define KDIM 3072
#define MDIM 3072
#define NDIM 1568
#define NPAD 1664            // 13 * 128; pad rows stay zero (static init)
#define RANK_OFF 0
#define CAM_OFF 96
#define FEAT_OFF 9504
#define FPB 1605632
#define FPI 50176

#define BM 128
#define BN 128
#define BK 64
#define NC (KDIM / BK)       // 48 k-chunks

// tile = 128 rows x 128B (64 fp16), XOR-swizzled 16B chunks; 4 tiles/stage
#define TILE_B 16384
#define STAGE_B 65536        // Ah | Al | Bh | Bl
#define SMEM_DYN (3 * STAGE_B)   // 196608

// ---- static scratch (no allocations allowed) ------------------------------
__device__ __align__(256) __half g_Ah[MDIM * KDIM];
__device__ __align__(256) __half g_Al[MDIM * KDIM];
__device__ __align__(256) __half g_Bh[NPAD * KDIM];   // pad rows never written -> 0
__device__ __align__(256) __half g_Bl[NPAD * KDIM];
__device__ float g_pooled[NBR * BATCH * 1024];
__device__ float g_h[NBR * BATCH * 512];

// ---- PTX helpers ----------------------------------------------------------
__device__ __forceinline__ uint32_t smem_u32(const void* p) {
    uint32_t a;
    asm("{ .reg .u64 t; cvta.to.shared.u64 t, %1; cvt.u32.u64 %0, t; }" : "=r"(a) : "l"(p));
    return a;
}
__device__ __forceinline__ void cp16(uint32_t dst, const void* src) {
    asm volatile("cp.async.cg.shared.global [%0], [%1], 16;" :: "r"(dst), "l"(src));
}
__device__ __forceinline__ void ldmx4(uint32_t* r, uint32_t a) {
    asm volatile("ldmatrix.sync.aligned.m8n8.x4.shared.b16 {%0,%1,%2,%3}, [%4];"
        : "=r"(r[0]), "=r"(r[1]), "=r"(r[2]), "=r"(r[3]) : "r"(a));
}
__device__ __forceinline__ void ldmx2(uint32_t* r, uint32_t a) {
    asm volatile("ldmatrix.sync.aligned.m8n8.x2.shared.b16 {%0,%1}, [%2];"
        : "=r"(r[0]), "=r"(r[1]) : "r"(a));
}
__device__ __forceinline__ void mma16816(float* c, const uint32_t* a, const uint32_t* b) {
    asm volatile("mma.sync.aligned.m16n8k16.row.col.f32.f16.f16.f32 "
        "{%0,%1,%2,%3}, {%4,%5,%6,%7}, {%8,%9}, {%0,%1,%2,%3};"
        : "+f"(c[0]), "+f"(c[1]), "+f"(c[2]), "+f"(c[3])
        : "r"(a[0]), "r"(a[1]), "r"(a[2]), "r"(a[3]), "r"(b[0]), "r"(b[1]));
}
__device__ __forceinline__ void mma16816h(uint32_t* c, const uint32_t* a, const uint32_t* b) {
    asm volatile("mma.sync.aligned.m16n8k16.row.col.f16.f16.f16.f16 "
        "{%0,%1}, {%2,%3,%4,%5}, {%6,%7}, {%0,%1};"
        : "+r"(c[0]), "+r"(c[1])
        : "r"(a[0]), "r"(a[1]), "r"(a[2]), "r"(a[3]), "r"(b[0]), "r"(b[1]));
}

// ---------------------------------------------------------------------------
// Kernel 1: Wb fp32 -> fp16 (hi, lo)
// ---------------------------------------------------------------------------
__global__ __launch_bounds__(256) void conv_a_kernel(const float* __restrict__ Wb) {
    int i2 = (blockIdx.x * 256 + threadIdx.x) * 2;
    if (i2 >= MDIM * KDIM) return;
    float2 v = *(const float2*)(Wb + i2);
    __half h0 = __float2half(v.x), h1 = __float2half(v.y);
    __half l0 = __float2half(v.x - __half2float(h0));
    __half l1 = __float2half(v.y - __half2float(h1));
    *(__half2*)(g_Ah + i2) = __half2(h0, h1);
    *(__half2*)(g_Al + i2) = __half2(l0, l1);
}

// ---------------------------------------------------------------------------
// Kernel 2: fused im2col + fp16 split: Bt[n][k], k = c*1024 + kh*32 + kw
// ---------------------------------------------------------------------------
__global__ __launch_bounds__(256) void im2col_kernel(const float* __restrict__ x) {
    int i2 = (blockIdx.x * 256 + threadIdx.x) * 2;
    if (i2 >= NDIM * KDIM) return;
    int n = i2 / KDIM;
    int k = i2 - n * KDIM;          // even
    int c = k >> 10, r = k & 1023, kh = r >> 5, kw = r & 31;
    int b = n / 49, t = n - b * 49, ii = t / 7, jj = t - ii * 7;
    const float* src = x + ((size_t)(b * 3 + c) * 224 + ii * 32 + kh) * 224 + jj * 32 + kw;
    float2 v = *(const float2*)src;
    __half h0 = __float2half(v.x), h1 = __float2half(v.y);
    __half l0 = __float2half(v.x - __half2float(h0));
    __half l1 = __float2half(v.y - __half2float(h1));
    *(__half2*)(g_Bh + i2) = __half2(h0, h1);
    *(__half2*)(g_Bl + i2) = __half2(l0, l1);
}

// ---------------------------------------------------------------------------
// Kernel 3: GEMM 128x128x64 per CTA, 8 warps (2m x 4n), 3-stage cp.async
// ---------------------------------------------------------------------------
__global__ __launch_bounds__(256, 1) void gemm_mma_kernel(const float* __restrict__ bias,
                                                          float* __restrict__ out) {
    extern __shared__ char smem[];
    const uint32_t s0 = smem_u32(smem);

    const int tid = threadIdx.x;
    const int wid = tid >> 5;
    const int lane = tid & 31;
    const int mBase = blockIdx.y * BM;
    const int nBase = blockIdx.x * BN;

    // ---- cp.async mapping: chunk = tid&7 (16B within row), rowbase = tid>>3
    const int lc = tid & 7;
    const int rb = tid >> 3;                   // 0..31; rows rb + 32q
    const uint32_t cs = (uint32_t)((lc ^ (rb & 7)) << 4);   // swizzled chunk
    const uint32_t rOff = (uint32_t)(rb * 128);
    const __half* gAh = g_Ah + (size_t)(mBase + rb) * KDIM + lc * 8;
    const __half* gAl = g_Al + (size_t)(mBase + rb) * KDIM + lc * 8;
    const __half* gBh = g_Bh + (size_t)(nBase + rb) * KDIM + lc * 8;
    const __half* gBl = g_Bl + (size_t)(nBase + rb) * KDIM + lc * 8;

#define ISSUE(kt) do {                                                          \
        const uint32_t st = s0 + (uint32_t)(((kt) % 3) * STAGE_B);              \
        const int k0 = (kt) * BK;                                               \
        _Pragma("unroll")                                                       \
        for (int q = 0; q < 4; q++) {                                           \
            const uint32_t d = st + rOff + q * 4096 + cs;                       \
            const size_t g = (size_t)q * 32 * KDIM + k0;                        \
            cp16(d,          gAh + g);                                          \
            cp16(d + 16384,  gAl + g);                                          \
            cp16(d + 32768,  gBh + g);                                          \
            cp16(d + 49152,  gBl + g);                                          \
        }                                                                       \
        asm volatile("cp.async.commit_group;");                                 \
    } while (0)

    // ---- accumulators ------------------------------------------------------
    float acc[4][4][4];
    uint32_t acch[4][4][2];
#pragma unroll
    for (int i = 0; i < 4; i++)
#pragma unroll
        for (int j = 0; j < 4; j++) {
#pragma unroll
            for (int q = 0; q < 4; q++) acc[i][j][q] = 0.f;
            acch[i][j][0] = 0u; acch[i][j][1] = 0u;
        }

    // ---- ldmatrix addressing ----------------------------------------------
    const int wm = wid & 1;             // 64-row half
    const int wn = wid >> 1;            // 32-col quarter
    const uint32_t aRowOff = (uint32_t)((wm * 64 + (lane & 15)) * 128);
    const uint32_t bRowOff = (uint32_t)(32768 + (wn * 32 + (lane & 7)) * 128);
    const int xorL = lane & 7;
    const int hiA = lane >> 4;          // 0/1 (x4: which 16B chunk)
    const int hiB = (lane >> 3) & 1;    // 0/1 (x2)

    ISSUE(0);
    ISSUE(1);
    asm volatile("cp.async.wait_group 1;");
    __syncthreads();

    for (int kt = 0; kt < NC; kt++) {
        if (kt + 2 < NC) ISSUE(kt + 2);
        else asm volatile("cp.async.commit_group;");

        const uint32_t sb = s0 + (uint32_t)((kt % 3) * STAGE_B);

#pragma unroll
        for (int ks = 0; ks < 4; ks++) {
            const uint32_t swA = (uint32_t)(((2 * ks + hiA) ^ xorL) << 4);
            const uint32_t swB = (uint32_t)(((2 * ks + hiB) ^ xorL) << 4);
            uint32_t ah[4][4], al[4][4], bh[4][2], bl[4][2];
#pragma unroll
            for (int mf = 0; mf < 4; mf++) ldmx4(ah[mf], sb + aRowOff + mf * 2048 + swA);
#pragma unroll
            for (int nf = 0; nf < 4; nf++) ldmx2(bh[nf], sb + bRowOff + nf * 1024 + swB);
#pragma unroll
            for (int mf = 0; mf < 4; mf++) ldmx4(al[mf], sb + 16384 + aRowOff + mf * 2048 + swA);
#pragma unroll
            for (int nf = 0; nf < 4; nf++) ldmx2(bl[nf], sb + 16384 + bRowOff + nf * 1024 + swB);

#pragma unroll
            for (int mf = 0; mf < 4; mf++)
#pragma unroll
                for (int nf = 0; nf < 4; nf++) {
                    mma16816(acc[mf][nf], ah[mf], bh[nf]);
                    mma16816h(acch[mf][nf], ah[mf], bl[nf]);
                    mma16816h(acch[mf][nf], al[mf], bh[nf]);
                }
        }
        asm volatile("cp.async.wait_group 1;");
        __syncthreads();
    }

    // ---- merge fp16 accumulators, bias, scatter to feature layout ----------
#pragma unroll
    for (int mf = 0; mf < 4; mf++) {
        const int m0 = mBase + wm * 64 + mf * 16 + (lane >> 2);
        const int m1 = m0 + 8;
        const float bv0 = bias[m0], bv1 = bias[m1];
        float* ob0 = out + FEAT_OFF + (size_t)(m0 >> 10) * FPB + (size_t)(m0 & 1023) * 49;
        float* ob1 = out + FEAT_OFF + (size_t)(m1 >> 10) * FPB + (size_t)(m1 & 1023) * 49;
#pragma unroll
        for (int nf = 0; nf < 4; nf++) {
            const int n = nBase + wn * 32 + nf * 8 + (lane & 3) * 2;
            __half2 lo01 = *(__half2*)&acch[mf][nf][0];
            __half2 lo23 = *(__half2*)&acch[mf][nf][1];
            float v0 = acc[mf][nf][0] + __low2float(lo01);
            float v1 = acc[mf][nf][1] + __high2float(lo01);
            float v2 = acc[mf][nf][2] + __low2float(lo23);
            float v3 = acc[mf][nf][3] + __high2float(lo23);
            if (n < NDIM) {
                int b0 = n / 49,       sA = n - b0 * 49;
                int b1 = (n + 1) / 49, sB = (n + 1) - b1 * 49;
                ob0[(size_t)b0 * FPI + sA] = v0 + bv0;
                ob0[(size_t)b1 * FPI + sB] = v1 + bv0;
                ob1[(size_t)b0 * FPI + sA] = v2 + bv1;
                ob1[(size_t)b1 * FPI + sB] = v3 + bv1;
            }
        }
    }
#undef ISSUE
}

// ---------------------------------------------------------------------------
// Kernel 4: global average pool -> g_pooled[n][b][1024]  (grid 96 x 4)
// ---------------------------------------------------------------------------
__global__ __launch_bounds__(256) void gap_kernel(const float* __restrict__ out) {
    const int n = blockIdx.x >> 5, b = blockIdx.x & 31;
    const int ch = blockIdx.y * 256 + threadIdx.x;
    const float* fo = out + FEAT_OFF + (size_t)n * FPB + (size_t)b * FPI + (size_t)ch * 49;
    float s = 0.f;
#pragma unroll
    for (int q = 0; q < 49; q++) s += fo[q];
    g_pooled[(n * 32 + b) * 1024 + ch] = s * (1.0f / 49.0f);
}

// ---------------------------------------------------------------------------
// Kernel 5: Linear(1024,512)+ReLU, weight-streamed
// ---------------------------------------------------------------------------
__global__ __launch_bounds__(256) void mlp1_kernel(const float* __restrict__ p1w,
                                                   const float* __restrict__ p1b) {
    const int branch = blockIdx.y;
    const int wid = threadIdx.x >> 5, lane = threadIdx.x & 31;
    const int j = blockIdx.x * 8 + wid;
    const float* w = p1w + (size_t)(branch * 512 + j) * 1024;
    float wr[32];
#pragma unroll
    for (int t = 0; t < 32; t++) wr[t] = w[t * 32 + lane];
    const float bj = p1b[branch * 512 + j];
    for (int b = 0; b < 32; b++) {
        const float* pp = g_pooled + (branch * 32 + b) * 1024;
        float s = 0.f;
#pragma unroll
        for (int t = 0; t < 32; t++) s = fmaf(wr[t], pp[t * 32 + lane], s);
#pragma unroll
        for (int off = 16; off; off >>= 1) s += __shfl_xor_sync(0xffffffffu, s, off);
        if (lane == 0) g_h[(branch * 32 + b) * 512 + j] = fmaxf(s + bj, 0.f);
    }
}

// ---------------------------------------------------------------------------
// Kernel 6: Linear(512,2) + softmax[:,1] -> ranking
// ---------------------------------------------------------------------------
__global__ __launch_bounds__(256) void mlp2_kernel(const float* __restrict__ p2w,
                                                   const float* __restrict__ p2b,
                                                   float* __restrict__ out) {
    const int branch = blockIdx.x;
    const int wid = threadIdx.x >> 5, lane = threadIdx.x & 31;
    const float* w0 = p2w + branch * 1024;
    const float* w1 = w0 + 512;
    for (int b = wid; b < 32; b += 8) {
        const float* h = g_h + (branch * 32 + b) * 512;
        float s0 = 0.f, s1 = 0.f;
        for (int t = lane; t < 512; t += 32) {
            float hv = h[t];
            s0 = fmaf(hv, w0[t], s0);
            s1 = fmaf(hv, w1[t], s1);
        }
#pragma unroll
        for (int off = 16; off; off >>= 1) {
            s0 += __shfl_xor_sync(0xffffffffu, s0, off);
            s1 += __shfl_xor_sync(0xffffffffu, s1, off);
        }
        if (lane == 0) {
            float l0 = s0 + p2b[branch * 2 + 0];
            float l1 = s1 + p2b[branch * 2 + 1];
            float mx = fmaxf(l0, l1);
            float e0 = expf(l0 - mx), e1 = expf(l1 - mx);
            out[RANK_OFF + b * 3 + branch] = e1 / (e0 + e1);
        }
    }
}

// ---------------------------------------------------------------------------
// Kernel 7: CAM — 98 dot-products of length 1024 per (branch,image)
// ---------------------------------------------------------------------------
__global__ __launch_bounds__(256) void cam_kernel(const float* __restrict__ out_r,
                                                  const float* __restrict__ clsw,
                                                  float* __restrict__ out_w) {
    __shared__ float wts[2048];
    __shared__ float tile[128 * 49];
    const int n = blockIdx.x >> 5, b = blockIdx.x & 31;
    const int tid = threadIdx.x, w = tid >> 5, lane = tid & 31;
    const float* f = out_r + FEAT_OFF + (size_t)n * FPB + (size_t)b * FPI;

    for (int i = tid; i < 2048; i += 256) wts[i] = clsw[n * 2048 + i];

    const int nd = (w < 2) ? 13 : 12;
    float acc[13];
#pragma unroll
    for (int i = 0; i < 13; i++) acc[i] = 0.f;

    for (int ch = 0; ch < 8; ch++) {
        __syncthreads();
        for (int i = tid; i < 128 * 49; i += 256) tile[i] = f[ch * (128 * 49) + i];
        __syncthreads();
#pragma unroll
        for (int di = 0; di < 13; di++) {
            if (di >= nd) break;
            int d = w + di * 8;
            int cls = d / 49, s = d - cls * 49;
            const float* wp = wts + cls * 1024 + ch * 128;
            float a = acc[di];
#pragma unroll
            for (int o4 = 0; o4 < 4; o4++)
                a = fmaf(wp[o4 * 32 + lane], tile[(o4 * 32 + lane) * 49 + s], a);
            acc[di] = a;
        }
    }
#pragma unroll
    for (int di = 0; di < 13; di++) {
        if (di >= nd) break;
        float a = acc[di];
#pragma unroll
        for (int off = 16; off; off >>= 1) a += __shfl_xor_sync(0xffffffffu, a, off);
        if (lane == 0) {
            int d = w + di * 8;
            int cls = d / 49, s = d - cls * 49;
            out_w[CAM_OFF + (n * 2 + cls) * 1568 + b * 49 + s] = fmaxf(a, 0.f);
        }
    }
}

// ---------------------------------------------------------------------------
// Launch
// ---------------------------------------------------------------------------
extern "C" void kernel_launch(void* const* d_in, const int* in_sizes, int n_in,
                              void* d_out, int out_size) {
    const float* x    = (const float*)d_in[0];
    const float* Wb   = (const float*)d_in[1];
    const float* bb   = (const float*)d_in[2];
    const float* p1w  = (const float*)d_in[3];
    const float* p1b  = (const float*)d_in[4];
    const float* p2w  = (const float*)d_in[5];
    const float* p2b  = (const float*)d_in[6];
    const float* clsw = (const float*)d_in[7];
    float* out = (float*)d_out;

    conv_a_kernel<<<(MDIM * KDIM / 2 + 255) / 256, 256>>>(Wb);
    im2col_kernel<<<(NDIM * KDIM / 2 + 255) / 256, 256>>>(x);

    cudaFuncSetAttribute(gemm_mma_kernel, cudaFuncAttributeMaxDynamicSharedMemorySize, SMEM_DYN);
    dim3 ggrid(NPAD / BN, MDIM / BM);   // (13, 24)
    gemm_mma_kernel<<<ggrid, 256, SMEM_DYN>>>(bb, out);

    gap_kernel<<<dim3(NBR * BATCH, 4), 256>>>(out);
    mlp1_kernel<<<dim3(64, NBR), 256>>>(p1w, p1b);
    mlp2_kernel<<<NBR, 256>>>(p2w, p2b, out);
    cam_kernel<<<NBR * BATCH, 256>>>(out, clsw, out);
}

// round 7
// speedup vs baseline: 3.6741x; 1.0529x over previous
#include <cuda_runtime.h>
#include <cuda_fp16.h>
#include <math.h>
#include <stdint.h>

// ---------------------------------------------------------------------------
// RankingCNN: conv(s32,k32) == GEMM C[3072,1568] = Wb[3072,3072] @ P[3072,1568]
// fp32 via fp16 split on legacy tensor cores (mma.sync.m16n8k16):
//   C = Ah*Bh (fp32 acc) + [Ah*Bl + Al*Bh] (fp16 acc, merged at end)
// R7: BM=64 tiles, 4-stage BK=32 pipeline, 2 CTAs/SM (4 warps/SMSP) to kill
// wave quantization (624 CTAs / 296 slots) and saturate the tensor pipe.
// ---------------------------------------------------------------------------

#define NBR 3
#define BATCH 32
#define KDIM 3072
#define MDIM 3072
#define NDIM 1568
#define NPAD 1664            // 13 * 128; pad rows stay zero (static init)
#define RANK_OFF 0
#define CAM_OFF 96
#define FEAT_OFF 9504
#define FPB 1605632
#define FPI 50176

#define BM 64
#define BN 128
#define BK 32
#define NC (KDIM / BK)       // 96 k-chunks

// rows are 64B (32 fp16); swizzle: 16B-chunk index ^= (row>>1)&3
#define A_T 4096             // one A tile (64 x 64B)
#define B_T 8192             // one B tile (128 x 64B)
#define STAGE_B 24576        // Ah | Al | Bh | Bl
#define NSTAGE 4
#define SMEM_DYN (NSTAGE * STAGE_B)   // 98304

// ---- static scratch (no allocations allowed) ------------------------------
__device__ __align__(256) __half g_Ah[MDIM * KDIM];
__device__ __align__(256) __half g_Al[MDIM * KDIM];
__device__ __align__(256) __half g_Bh[NPAD * KDIM];   // pad rows never written -> 0
__device__ __align__(256) __half g_Bl[NPAD * KDIM];
__device__ float g_pooled[NBR * BATCH * 1024];
__device__ float g_h[NBR * BATCH * 512];

// ---- PTX helpers ----------------------------------------------------------
__device__ __forceinline__ uint32_t smem_u32(const void* p) {
    uint32_t a;
    asm("{ .reg .u64 t; cvta.to.shared.u64 t, %1; cvt.u32.u64 %0, t; }" : "=r"(a) : "l"(p));
    return a;
}
__device__ __forceinline__ void cp16(uint32_t dst, const void* src) {
    asm volatile("cp.async.cg.shared.global [%0], [%1], 16;" :: "r"(dst), "l"(src));
}
__device__ __forceinline__ void ldmx4(uint32_t* r, uint32_t a) {
    asm volatile("ldmatrix.sync.aligned.m8n8.x4.shared.b16 {%0,%1,%2,%3}, [%4];"
        : "=r"(r[0]), "=r"(r[1]), "=r"(r[2]), "=r"(r[3]) : "r"(a));
}
__device__ __forceinline__ void ldmx2(uint32_t* r, uint32_t a) {
    asm volatile("ldmatrix.sync.aligned.m8n8.x2.shared.b16 {%0,%1}, [%2];"
        : "=r"(r[0]), "=r"(r[1]) : "r"(a));
}
__device__ __forceinline__ void mma16816(float* c, const uint32_t* a, const uint32_t* b) {
    asm volatile("mma.sync.aligned.m16n8k16.row.col.f32.f16.f16.f32 "
        "{%0,%1,%2,%3}, {%4,%5,%6,%7}, {%8,%9}, {%0,%1,%2,%3};"
        : "+f"(c[0]), "+f"(c[1]), "+f"(c[2]), "+f"(c[3])
        : "r"(a[0]), "r"(a[1]), "r"(a[2]), "r"(a[3]), "r"(b[0]), "r"(b[1]));
}
__device__ __forceinline__ void mma16816h(uint32_t* c, const uint32_t* a, const uint32_t* b) {
    asm volatile("mma.sync.aligned.m16n8k16.row.col.f16.f16.f16.f16 "
        "{%0,%1}, {%2,%3,%4,%5}, {%6,%7}, {%0,%1};"
        : "+r"(c[0]), "+r"(c[1])
        : "r"(a[0]), "r"(a[1]), "r"(a[2]), "r"(a[3]), "r"(b[0]), "r"(b[1]));
}

// ---------------------------------------------------------------------------
// Kernel 1: Wb fp32 -> fp16 (hi, lo)
// ---------------------------------------------------------------------------
__global__ __launch_bounds__(256) void conv_a_kernel(const float* __restrict__ Wb) {
    int i2 = (blockIdx.x * 256 + threadIdx.x) * 2;
    if (i2 >= MDIM * KDIM) return;
    float2 v = *(const float2*)(Wb + i2);
    __half h0 = __float2half(v.x), h1 = __float2half(v.y);
    __half l0 = __float2half(v.x - __half2float(h0));
    __half l1 = __float2half(v.y - __half2float(h1));
    *(__half2*)(g_Ah + i2) = __half2(h0, h1);
    *(__half2*)(g_Al + i2) = __half2(l0, l1);
}

// ---------------------------------------------------------------------------
// Kernel 2: fused im2col + fp16 split: Bt[n][k], k = c*1024 + kh*32 + kw
// ---------------------------------------------------------------------------
__global__ __launch_bounds__(256) void im2col_kernel(const float* __restrict__ x) {
    int i2 = (blockIdx.x * 256 + threadIdx.x) * 2;
    if (i2 >= NDIM * KDIM) return;
    int n = i2 / KDIM;
    int k = i2 - n * KDIM;          // even
    int c = k >> 10, r = k & 1023, kh = r >> 5, kw = r & 31;
    int b = n / 49, t = n - b * 49, ii = t / 7, jj = t - ii * 7;
    const float* src = x + ((size_t)(b * 3 + c) * 224 + ii * 32 + kh) * 224 + jj * 32 + kw;
    float2 v = *(const float2*)src;
    __half h0 = __float2half(v.x), h1 = __float2half(v.y);
    __half l0 = __float2half(v.x - __half2float(h0));
    __half l1 = __float2half(v.y - __half2float(h1));
    *(__half2*)(g_Bh + i2) = __half2(h0, h1);
    *(__half2*)(g_Bl + i2) = __half2(l0, l1);
}

// ---------------------------------------------------------------------------
// Kernel 3: GEMM 64x128x32 per CTA, 8 warps (2m x 4n, warp 32x32), 4 stages
// ---------------------------------------------------------------------------
__global__ __launch_bounds__(256, 2) void gemm_mma_kernel(const float* __restrict__ bias,
                                                          float* __restrict__ out) {
    extern __shared__ char smem[];
    const uint32_t s0 = smem_u32(smem);

    const int tid = threadIdx.x;
    const int wid = tid >> 5;
    const int lane = tid & 31;
    const int mBase = blockIdx.y * BM;
    const int nBase = blockIdx.x * BN;

    // ---- cp.async mapping: thread t -> row = t>>2, 16B chunk = t&3 ---------
    const int aRow = tid >> 2;                 // 0..63
    const int c = tid & 3;
    const uint32_t cSw = (uint32_t)((c ^ ((aRow >> 1) & 3)) << 4);
    const uint32_t aOff = (uint32_t)(aRow * 64) + cSw;    // same swizzle both B rows
    const __half* gAh = g_Ah + (size_t)(mBase + aRow) * KDIM + c * 8;
    const __half* gAl = g_Al + (size_t)(mBase + aRow) * KDIM + c * 8;
    const __half* gBh = g_Bh + (size_t)(nBase + aRow) * KDIM + c * 8;
    const __half* gBl = g_Bl + (size_t)(nBase + aRow) * KDIM + c * 8;
    const size_t bJump = (size_t)64 * KDIM;

#define ISSUE(kt) do {                                                          \
        const uint32_t st = s0 + (uint32_t)(((kt) & 3) * STAGE_B);              \
        const int k0 = (kt) * BK;                                               \
        cp16(st + aOff,                 gAh + k0);                              \
        cp16(st + A_T + aOff,           gAl + k0);                              \
        cp16(st + 2*A_T + aOff,         gBh + k0);                              \
        cp16(st + 2*A_T + aOff + 4096,  gBh + bJump + k0);                      \
        cp16(st + 2*A_T + B_T + aOff,        gBl + k0);                         \
        cp16(st + 2*A_T + B_T + aOff + 4096, gBl + bJump + k0);                 \
        asm volatile("cp.async.commit_group;");                                 \
    } while (0)

    // ---- accumulators ------------------------------------------------------
    float acc[2][4][4];
    uint32_t acch[2][4][2];
#pragma unroll
    for (int i = 0; i < 2; i++)
#pragma unroll
        for (int j = 0; j < 4; j++) {
#pragma unroll
            for (int q = 0; q < 4; q++) acc[i][j][q] = 0.f;
            acch[i][j][0] = 0u; acch[i][j][1] = 0u;
        }

    // ---- ldmatrix addressing ----------------------------------------------
    const int wm = wid & 1;             // 32-row half
    const int wn = wid >> 1;            // 32-col quarter
    // A x4: row = wm*32 + mf*16 + (lane&15); chunk = ks*2 + (lane>>4)
    const int aR = wm * 32 + (lane & 15);
    const int aHi = lane >> 4;
    // B x2: row = wn*32 + nf*8 + (lane&7); chunk = ks*2 + ((lane>>3)&1)
    const int bR = wn * 32 + (lane & 7);
    const int bHi = (lane >> 3) & 1;

    ISSUE(0); ISSUE(1); ISSUE(2);

    for (int kt = 0; kt < NC; kt++) {
        asm volatile("cp.async.wait_group 2;");
        __syncthreads();
        if (kt + 3 < NC) ISSUE(kt + 3);
        else asm volatile("cp.async.commit_group;");

        const uint32_t sb = s0 + (uint32_t)((kt & 3) * STAGE_B);

#pragma unroll
        for (int ks = 0; ks < 2; ks++) {
            uint32_t ah[2][4], al[2][4], bh[4][2], bl[4][2];
#pragma unroll
            for (int mf = 0; mf < 2; mf++) {
                const int row = aR + mf * 16;
                const uint32_t ad = sb + (uint32_t)(row * 64)
                    + (uint32_t)((((ks * 2 + aHi)) ^ ((row >> 1) & 3)) << 4);
                ldmx4(ah[mf], ad);
                ldmx4(al[mf], ad + A_T);
            }
#pragma unroll
            for (int nf = 0; nf < 4; nf++) {
                const int row = bR + nf * 8;
                const uint32_t bd = sb + 2 * A_T + (uint32_t)(row * 64)
                    + (uint32_t)((((ks * 2 + bHi)) ^ ((row >> 1) & 3)) << 4);
                ldmx2(bh[nf], bd);
                ldmx2(bl[nf], bd + B_T);
            }
#pragma unroll
            for (int mf = 0; mf < 2; mf++)
#pragma unroll
                for (int nf = 0; nf < 4; nf++) {
                    mma16816(acc[mf][nf], ah[mf], bh[nf]);
                    mma16816h(acch[mf][nf], ah[mf], bl[nf]);
                    mma16816h(acch[mf][nf], al[mf], bh[nf]);
                }
        }
    }

    // ---- merge fp16 accumulators, bias, scatter to feature layout ----------
#pragma unroll
    for (int mf = 0; mf < 2; mf++) {
        const int m0 = mBase + wm * 32 + mf * 16 + (lane >> 2);
        const int m1 = m0 + 8;
        const float bv0 = bias[m0], bv1 = bias[m1];
        float* ob0 = out + FEAT_OFF + (size_t)(m0 >> 10) * FPB + (size_t)(m0 & 1023) * 49;
        float* ob1 = out + FEAT_OFF + (size_t)(m1 >> 10) * FPB + (size_t)(m1 & 1023) * 49;
#pragma unroll
        for (int nf = 0; nf < 4; nf++) {
            const int n = nBase + wn * 32 + nf * 8 + (lane & 3) * 2;
            __half2 lo01 = *(__half2*)&acch[mf][nf][0];
            __half2 lo23 = *(__half2*)&acch[mf][nf][1];
            float v0 = acc[mf][nf][0] + __low2float(lo01);
            float v1 = acc[mf][nf][1] + __high2float(lo01);
            float v2 = acc[mf][nf][2] + __low2float(lo23);
            float v3 = acc[mf][nf][3] + __high2float(lo23);
            if (n < NDIM) {
                int b0 = n / 49,       sA = n - b0 * 49;
                int b1 = (n + 1) / 49, sB = (n + 1) - b1 * 49;
                ob0[(size_t)b0 * FPI + sA] = v0 + bv0;
                ob0[(size_t)b1 * FPI + sB] = v1 + bv0;
                ob1[(size_t)b0 * FPI + sA] = v2 + bv1;
                ob1[(size_t)b1 * FPI + sB] = v3 + bv1;
            }
        }
    }
#undef ISSUE
}

// ---------------------------------------------------------------------------
// Kernel 4: global average pool -> g_pooled[n][b][1024]  (grid 96 x 4)
// ---------------------------------------------------------------------------
__global__ __launch_bounds__(256) void gap_kernel(const float* __restrict__ out) {
    const int n = blockIdx.x >> 5, b = blockIdx.x & 31;
    const int ch = blockIdx.y * 256 + threadIdx.x;
    const float* fo = out + FEAT_OFF + (size_t)n * FPB + (size_t)b * FPI + (size_t)ch * 49;
    float s = 0.f;
#pragma unroll
    for (int q = 0; q < 49; q++) s += fo[q];
    g_pooled[(n * 32 + b) * 1024 + ch] = s * (1.0f / 49.0f);
}

// ---------------------------------------------------------------------------
// Kernel 5: Linear(1024,512)+ReLU, weight-streamed
// ---------------------------------------------------------------------------
__global__ __launch_bounds__(256) void mlp1_kernel(const float* __restrict__ p1w,
                                                   const float* __restrict__ p1b) {
    const int branch = blockIdx.y;
    const int wid = threadIdx.x >> 5, lane = threadIdx.x & 31;
    const int j = blockIdx.x * 8 + wid;
    const float* w = p1w + (size_t)(branch * 512 + j) * 1024;
    float wr[32];
#pragma unroll
    for (int t = 0; t < 32; t++) wr[t] = w[t * 32 + lane];
    const float bj = p1b[branch * 512 + j];
    for (int b = 0; b < 32; b++) {
        const float* pp = g_pooled + (branch * 32 + b) * 1024;
        float s = 0.f;
#pragma unroll
        for (int t = 0; t < 32; t++) s = fmaf(wr[t], pp[t * 32 + lane], s);
#pragma unroll
        for (int off = 16; off; off >>= 1) s += __shfl_xor_sync(0xffffffffu, s, off);
        if (lane == 0) g_h[(branch * 32 + b) * 512 + j] = fmaxf(s + bj, 0.f);
    }
}

// ---------------------------------------------------------------------------
// Kernel 6: Linear(512,2) + softmax[:,1] -> ranking
// ---------------------------------------------------------------------------
__global__ __launch_bounds__(256) void mlp2_kernel(const float* __restrict__ p2w,
                                                   const float* __restrict__ p2b,
                                                   float* __restrict__ out) {
    const int branch = blockIdx.x;
    const int wid = threadIdx.x >> 5, lane = threadIdx.x & 31;
    const float* w0 = p2w + branch * 1024;
    const float* w1 = w0 + 512;
    for (int b = wid; b < 32; b += 8) {
        const float* h = g_h + (branch * 32 + b) * 512;
        float s0 = 0.f, s1 = 0.f;
        for (int t = lane; t < 512; t += 32) {
            float hv = h[t];
            s0 = fmaf(hv, w0[t], s0);
            s1 = fmaf(hv, w1[t], s1);
        }
#pragma unroll
        for (int off = 16; off; off >>= 1) {
            s0 += __shfl_xor_sync(0xffffffffu, s0, off);
            s1 += __shfl_xor_sync(0xffffffffu, s1, off);
        }
        if (lane == 0) {
            float l0 = s0 + p2b[branch * 2 + 0];
            float l1 = s1 + p2b[branch * 2 + 1];
            float mx = fmaxf(l0, l1);
            float e0 = expf(l0 - mx), e1 = expf(l1 - mx);
            out[RANK_OFF + b * 3 + branch] = e1 / (e0 + e1);
        }
    }
}

// ---------------------------------------------------------------------------
// Kernel 7: CAM — 98 dot-products of length 1024 per (branch,image)
// ---------------------------------------------------------------------------
__global__ __launch_bounds__(256) void cam_kernel(const float* __restrict__ out_r,
                                                  const float* __restrict__ clsw,
                                                  float* __restrict__ out_w) {
    __shared__ float wts[2048];
    __shared__ float tile[128 * 49];
    const int n = blockIdx.x >> 5, b = blockIdx.x & 31;
    const int tid = threadIdx.x, w = tid >> 5, lane = tid & 31;
    const float* f = out_r + FEAT_OFF + (size_t)n * FPB + (size_t)b * FPI;

    for (int i = tid; i < 2048; i += 256) wts[i] = clsw[n * 2048 + i];

    const int nd = (w < 2) ? 13 : 12;
    float acc[13];
#pragma unroll
    for (int i = 0; i < 13; i++) acc[i] = 0.f;

    for (int ch = 0; ch < 8; ch++) {
        __syncthreads();
        for (int i = tid; i < 128 * 49; i += 256) tile[i] = f[ch * (128 * 49) + i];
        __syncthreads();
#pragma unroll
        for (int di = 0; di < 13; di++) {
            if (di >= nd) break;
            int d = w + di * 8;
            int cls = d / 49, s = d - cls * 49;
            const float* wp = wts + cls * 1024 + ch * 128;
            float a = acc[di];
#pragma unroll
            for (int o4 = 0; o4 < 4; o4++)
                a = fmaf(wp[o4 * 32 + lane], tile[(o4 * 32 + lane) * 49 + s], a);
            acc[di] = a;
        }
    }
#pragma unroll
    for (int di = 0; di < 13; di++) {
        if (di >= nd) break;
        float a = acc[di];
#pragma unroll
        for (int off = 16; off; off >>= 1) a += __shfl_xor_sync(0xffffffffu, a, off);
        if (lane == 0) {
            int d = w + di * 8;
            int cls = d / 49, s = d - cls * 49;
            out_w[CAM_OFF + (n * 2 + cls) * 1568 + b * 49 + s] = fmaxf(a, 0.f);
        }
    }
}

// ---------------------------------------------------------------------------
// Launch
// ---------------------------------------------------------------------------
extern "C" void kernel_launch(void* const* d_in, const int* in_sizes, int n_in,
                              void* d_out, int out_size) {
    const float* x    = (const float*)d_in[0];
    const float* Wb   = (const float*)d_in[1];
    const float* bb   = (const float*)d_in[2];
    const float* p1w  = (const float*)d_in[3];
    const float* p1b  = (const float*)d_in[4];
    const float* p2w  = (const float*)d_in[5];
    const float* p2b  = (const float*)d_in[6];
    const float* clsw = (const float*)d_in[7];
    float* out = (float*)d_out;

    conv_a_kernel<<<(MDIM * KDIM / 2 + 255) / 256, 256>>>(Wb);
    im2col_kernel<<<(NDIM * KDIM / 2 + 255) / 256, 256>>>(x);

    cudaFuncSetAttribute(gemm_mma_kernel, cudaFuncAttributeMaxDynamicSharedMemorySize, SMEM_DYN);
    dim3 ggrid(NPAD / BN, MDIM / BM);   // (13, 48)
    gemm_mma_kernel<<<ggrid, 256, SMEM_DYN>>>(bb, out);

    gap_kernel<<<dim3(NBR * BATCH, 4), 256>>>(out);
    mlp1_kernel<<<dim3(64, NBR), 256>>>(p1w, p1b);
    mlp2_kernel<<<NBR, 256>>>(p2w, p2b, out);
    cam_kernel<<<NBR * BATCH, 256>>>(out, clsw, out);
}